// round 17
// baseline (speedup 1.0000x reference)
#include <cuda_runtime.h>
#include <cuda_fp16.h>
#include <cstdint>

// ----------------------------------------------------------------------------
// Polynormer forward: N=100000, E=1.6M, D=256, H=4, C=64, L=3, OUT=64
// R17: resident-A fused GEMM — full 128x256 fp16 A tile lives in smem (64KB),
//      3 weight segments stream through a 3-stage B ring (98,304B total =
//      exactly 2 CTAs/SM). A L2 traffic per launch: 300MB -> 100MB.
//      Same warp tiles / occupancy / sync cadence as the proven R16 kernel.
// ----------------------------------------------------------------------------

#define NN 100000
#define EE 1600000
#define DD 256
#define HH 4
#define OUTD 64
#define NEG_SLOPE 0.2f
#define LNEPS 1e-5f

// ---------------- scratch (device globals; allocation-free) -----------------
__device__ __half g_xin [NN * DD];
__device__ __half g_xh  [NN * DD];
__device__ __half g_h   [NN * DD];
__device__ __half g_hgh [NN * DD];
__device__ __half g_xl  [NN * DD];
__device__ float  g_xloc[NN * DD];
__device__ __half g_wrh [655360];         // fp16 transposed: Wh|Wg|Wl (9) + Win
__device__ float  g_asrc[NN * HH];
__device__ float  g_adst[NN * HH];
__device__ float  g_attp[NN * HH * 4];
__device__ int    g_cnt   [NN];
__device__ int    g_rowptr[NN + 1];
__device__ int    g_cursor[NN];
__device__ int    g_srcs  [EE + NN];
__device__ int    g_bsum[128];
__device__ int    g_boff[128];

static inline int cdiv(int a, int b) { return (a + b - 1) / b; }

__device__ __forceinline__ uint32_t f2tf32(float f) {
    uint32_t u;
    asm("cvt.rna.tf32.f32 %0, %1;" : "=r"(u) : "f"(f));
    return u;
}

// ---------------- CSR build --------------------------------------------------
__global__ void k_init_cnt() {
    int i = blockIdx.x * blockDim.x + threadIdx.x;
    if (i < NN) g_cnt[i] = 1;  // self loop
}

__global__ void k_hist(const int* __restrict__ ei) {
    int i = blockIdx.x * blockDim.x + threadIdx.x;
    if (i < EE) atomicAdd(&g_cnt[ei[EE + i]], 1);
}

__global__ void k_scan1() {
    __shared__ int sh[1024];
    int t = threadIdx.x, b = blockIdx.x;
    int idx = b * 1024 + t;
    int v = (idx < NN) ? g_cnt[idx] : 0;
    sh[t] = v;
    for (int off = 1; off < 1024; off <<= 1) {
        __syncthreads();
        int u = (t >= off) ? sh[t - off] : 0;
        __syncthreads();
        sh[t] += u;
    }
    if (idx < NN) g_rowptr[idx + 1] = sh[t];
    if (t == 1023) g_bsum[b] = sh[t];
}

__global__ void k_scan2(int nb) {
    if (threadIdx.x == 0 && blockIdx.x == 0) {
        int acc = 0;
        for (int i = 0; i < nb; i++) { g_boff[i] = acc; acc += g_bsum[i]; }
    }
}

__global__ void k_scan3() {
    int idx = blockIdx.x * blockDim.x + threadIdx.x;
    if (idx == 0) { g_rowptr[0] = 0; g_cursor[0] = 0; }
    if (idx < NN) {
        int v = g_rowptr[idx + 1] + g_boff[idx >> 10];
        g_rowptr[idx + 1] = v;
        if (idx + 1 < NN) g_cursor[idx + 1] = v;
    }
}

__global__ void k_scatter(const int* __restrict__ ei) {
    int idx = blockIdx.x * blockDim.x + threadIdx.x;
    int src, dst;
    if (idx < EE)            { src = ei[idx]; dst = ei[EE + idx]; }
    else if (idx < EE + NN)  { src = idx - EE; dst = src; }
    else return;
    int pos = atomicAdd(&g_cursor[dst], 1);
    g_srcs[pos] = src;
}

// ---------------- weight fp16 + transpose to [n][k] --------------------------
__global__ void k_round(const float* __restrict__ Wh, const float* __restrict__ Wg,
                        const float* __restrict__ Wl, const float* __restrict__ Win) {
    int t = blockIdx.x * blockDim.x + threadIdx.x;
    if (t >= 655360) return;
    int m = t >> 16;
    int o = t & 65535;
    int n = o >> 8, k = o & 255;
    const float* src = (m < 3) ? (Wh + m * 65536)
                     : (m < 6) ? (Wg + (m - 3) * 65536)
                     : (m < 9) ? (Wl + (m - 6) * 65536)
                               : Win;
    g_wrh[t] = __float2half_rn(src[k * 256 + n]);
}

// ---------------- x_in fp32 -> fp16 ------------------------------------------
__global__ void k_xcvt(const float* __restrict__ x_in) {
    int i = blockIdx.x * blockDim.x + threadIdx.x;
    if (i >= NN * DD / 8) return;
    const float4* p = (const float4*)(x_in + (size_t)i * 8);
    float4 a = p[0], b = p[1];
    uint4 o;
    *(__half2*)&o.x = __float22half2_rn(make_float2(a.x, a.y));
    *(__half2*)&o.y = __float22half2_rn(make_float2(a.z, a.w));
    *(__half2*)&o.z = __float22half2_rn(make_float2(b.x, b.y));
    *(__half2*)&o.w = __float22half2_rn(make_float2(b.z, b.w));
    *(uint4*)&g_xin[(size_t)i * 8] = o;
}

// ---------------- MMA primitives ---------------------------------------------
#define GBM 128
#define GBN 128
#define GBK 16

__device__ __forceinline__ void mma_tf32(float* d, const uint32_t* a, const uint32_t* b) {
    asm volatile(
        "mma.sync.aligned.m16n8k8.row.col.f32.tf32.tf32.f32 "
        "{%0,%1,%2,%3}, {%4,%5,%6,%7}, {%8,%9}, {%0,%1,%2,%3};\n"
        : "+f"(d[0]), "+f"(d[1]), "+f"(d[2]), "+f"(d[3])
        : "r"(a[0]), "r"(a[1]), "r"(a[2]), "r"(a[3]), "r"(b[0]), "r"(b[1]));
}

__device__ __forceinline__ void mma_f16(float* d, const uint32_t* a, const uint32_t* b) {
    asm volatile(
        "mma.sync.aligned.m16n8k16.row.col.f32.f16.f16.f32 "
        "{%0,%1,%2,%3}, {%4,%5,%6,%7}, {%8,%9}, {%0,%1,%2,%3};\n"
        : "+f"(d[0]), "+f"(d[1]), "+f"(d[2]), "+f"(d[3])
        : "r"(a[0]), "r"(a[1]), "r"(a[2]), "r"(a[3]), "r"(b[0]), "r"(b[1]));
}

__device__ __forceinline__ void cpa16(uint32_t sa, const void* g, bool p) {
    int sz = p ? 16 : 0;
    asm volatile("cp.async.cg.shared.global [%0], [%1], 16, %2;\n"
                 :: "r"(sa), "l"(g), "r"(sz) : "memory");
}
#define CP_COMMIT() asm volatile("cp.async.commit_group;\n" ::: "memory")
#define CP_WAIT1()  asm volatile("cp.async.wait_group 1;\n" ::: "memory")

#define LDSM4(r0, r1, r2, r3, addr)                                            \
    asm volatile("ldmatrix.sync.aligned.m8n8.x4.shared.b16 {%0,%1,%2,%3}, [%4];" \
                 : "=r"(r0), "=r"(r1), "=r"(r2), "=r"(r3) : "r"(addr))

// ---------------- output GEMM: 128x64 tile (tf32, fp32 xloc) -----------------
__global__ void __launch_bounds__(256, 2) k_mmaO(
    const float* __restrict__ A, const float* __restrict__ B,
    const float* __restrict__ bias, float* __restrict__ C)
{
    __shared__ uint32_t As[2][128][GBK + 4];
    __shared__ uint32_t Bs[2][GBK][64 + 8];

    int tid  = threadIdx.x;
    int lane = tid & 31;
    int warp = tid >> 5;
    int wr = warp >> 1, wc = warp & 1;
    int lr = lane >> 2, lc = lane & 3;
    int rowBase = blockIdx.x * 128;

    int aRow = tid >> 1;
    int aK   = (tid & 1) << 3;
    int bRow = tid >> 4;
    int bCol = (tid & 15) << 2;

    float acc[2][4][4];
#pragma unroll
    for (int m = 0; m < 2; m++)
#pragma unroll
        for (int n = 0; n < 4; n++)
#pragma unroll
            for (int r = 0; r < 4; r++) acc[m][n][r] = 0.f;

    float aReg[8], bReg[4];
    const int NT = DD / GBK;   // 16

    {
        bool okA = (rowBase + aRow) < NN;
        const float* pA = A + (size_t)(rowBase + aRow) * DD + aK;
        float4 v0 = okA ? *(const float4*)pA       : make_float4(0,0,0,0);
        float4 v1 = okA ? *(const float4*)(pA + 4) : make_float4(0,0,0,0);
        aReg[0]=v0.x; aReg[1]=v0.y; aReg[2]=v0.z; aReg[3]=v0.w;
        aReg[4]=v1.x; aReg[5]=v1.y; aReg[6]=v1.z; aReg[7]=v1.w;
        float4 w = *(const float4*)&B[(size_t)bRow * OUTD + bCol];
        bReg[0]=w.x; bReg[1]=w.y; bReg[2]=w.z; bReg[3]=w.w;
    }
#pragma unroll
    for (int j = 0; j < 8; j++) As[0][aRow][aK + j]  = f2tf32(aReg[j]);
#pragma unroll
    for (int j = 0; j < 4; j++) Bs[0][bRow][bCol + j] = f2tf32(bReg[j]);
    __syncthreads();

    for (int kt = 0; kt < NT; kt++) {
        int buf = kt & 1;
        if (kt + 1 < NT) {
            bool okA = (rowBase + aRow) < NN;
            const float* pA = A + (size_t)(rowBase + aRow) * DD + (kt + 1) * GBK + aK;
            float4 v0 = okA ? *(const float4*)pA       : make_float4(0,0,0,0);
            float4 v1 = okA ? *(const float4*)(pA + 4) : make_float4(0,0,0,0);
            aReg[0]=v0.x; aReg[1]=v0.y; aReg[2]=v0.z; aReg[3]=v0.w;
            aReg[4]=v1.x; aReg[5]=v1.y; aReg[6]=v1.z; aReg[7]=v1.w;
            float4 w = *(const float4*)&B[(size_t)((kt + 1) * GBK + bRow) * OUTD + bCol];
            bReg[0]=w.x; bReg[1]=w.y; bReg[2]=w.z; bReg[3]=w.w;
        }
#pragma unroll
        for (int ks = 0; ks < 2; ks++) {
            int kb = ks * 8;
            uint32_t af[2][4], bf[4][2];
#pragma unroll
            for (int mt = 0; mt < 2; mt++) {
                int r = wr * 32 + mt * 16 + lr;
                af[mt][0] = As[buf][r    ][kb + lc];
                af[mt][1] = As[buf][r + 8][kb + lc];
                af[mt][2] = As[buf][r    ][kb + lc + 4];
                af[mt][3] = As[buf][r + 8][kb + lc + 4];
            }
#pragma unroll
            for (int nt = 0; nt < 4; nt++) {
                int c = wc * 32 + nt * 8 + lr;
                bf[nt][0] = Bs[buf][kb + lc    ][c];
                bf[nt][1] = Bs[buf][kb + lc + 4][c];
            }
#pragma unroll
            for (int mt = 0; mt < 2; mt++)
#pragma unroll
                for (int nt = 0; nt < 4; nt++)
                    mma_tf32(acc[mt][nt], af[mt], bf[nt]);
        }
        if (kt + 1 < NT) {
            int nb2 = 1 - buf;
#pragma unroll
            for (int j = 0; j < 8; j++) As[nb2][aRow][aK + j]  = f2tf32(aReg[j]);
#pragma unroll
            for (int j = 0; j < 4; j++) Bs[nb2][bRow][bCol + j] = f2tf32(bReg[j]);
        }
        __syncthreads();
    }

#pragma unroll
    for (int nt = 0; nt < 4; nt++) {
        int col = wc * 32 + nt * 8 + 2 * lc;
        float2 bb = *(const float2*)&bias[col];
#pragma unroll
        for (int mt = 0; mt < 2; mt++) {
            int row = rowBase + wr * 32 + mt * 16 + lr;
#pragma unroll
            for (int half = 0; half < 2; half++) {
                int rr = row + half * 8;
                if (rr < NN) {
                    float2 o;
                    o.x = acc[mt][nt][half * 2]     + bb.x;
                    o.y = acc[mt][nt][half * 2 + 1] + bb.y;
                    *(float2*)&C[(size_t)rr * OUTD + col] = o;
                }
            }
        }
    }
}

// ---------------- fp16 GEMM constants -----------------------------------------
#define GBK3 32
#define ST 3
#define TSTRH 40
#define TILE_H (128 * TSTRH)
#define SMEM3 (2 * ST * TILE_H * 2)
// resident-A kernel
#define ASTRH 264                       // A row stride (halves): 528B = 33x16B
#define BT_H  (128 * TSTRH)
#define SMEMR (128 * ASTRH * 2 + ST * BT_H * 2)   // 67584 + 30720 = 98304

// ---------------- input GEMM: fp16 ring (both operands), writes fp16 x -------
__global__ void __launch_bounds__(256, 2) k_mmaI16(
    const __half* __restrict__ A, const __half* __restrict__ W,
    const float* __restrict__ bias, __half* __restrict__ C)
{
    extern __shared__ __half smh[];
    uint32_t sbA = (uint32_t)__cvta_generic_to_shared(smh);
    uint32_t sbB = sbA + ST * TILE_H * 2;

    int tid  = threadIdx.x;
    int lane = tid & 31;
    int warp = tid >> 5;
    int wr = warp >> 2, wc = warp & 3;
    int lr = lane >> 2, lc = lane & 3;
    int rowBase = blockIdx.y * GBM;
    int colBase = blockIdx.x * GBN;

    int row = tid >> 1;
    int kp  = (tid & 1) * 16;
    bool okA = (rowBase + row) < NN;
    const __half* gA0 = A + (size_t)(rowBase + row) * DD + kp;
    const __half* gB0 = W + (size_t)(colBase + row) * DD + kp;
    uint32_t saBase = (row * TSTRH + kp) * 2;
    int aOff = (wr * 64 + (lane & 15)) * TSTRH + (lane >> 4) * 8;
    int bOff = (wc * 32 + (lane & 7) + ((lane >> 4) & 1) * 8) * TSTRH
             + ((lane >> 3) & 1) * 8;

    float acc[4][4][4];
#pragma unroll
    for (int m = 0; m < 4; m++)
#pragma unroll
        for (int n = 0; n < 4; n++)
#pragma unroll
            for (int r = 0; r < 4; r++) acc[m][n][r] = 0.f;

#define ISSUE(kt, s)                                                            \
    do {                                                                        \
        const __half* gA = gA0 + (kt) * GBK3;                                   \
        uint32_t sa = sbA + (s) * TILE_H * 2 + saBase;                          \
        cpa16(sa,      gA,     okA);                                            \
        cpa16(sa + 16, gA + 8, okA);                                            \
        const __half* gB = gB0 + (kt) * GBK3;                                   \
        uint32_t sb = sbB + (s) * TILE_H * 2 + saBase;                          \
        cpa16(sb,      gB,     true);                                           \
        cpa16(sb + 16, gB + 8, true);                                           \
        CP_COMMIT();                                                            \
    } while (0)

    ISSUE(0, 0);
    ISSUE(1, 1);

    const int NT = DD / GBK3;   // 8
    for (int kt = 0; kt < NT; kt++) {
        CP_WAIT1();
        __syncthreads();
        if (kt + 2 < NT) { ISSUE(kt + 2, (kt + 2) % ST); }
        else CP_COMMIT();
        int s = kt % ST;
        uint32_t aS = sbA + s * TILE_H * 2 + aOff * 2;
        uint32_t bS = sbB + s * TILE_H * 2 + bOff * 2;
#pragma unroll
        for (int kc = 0; kc < 2; kc++) {
            uint32_t af[4][4], bf[4][2];
#pragma unroll
            for (int mt = 0; mt < 4; mt++)
                LDSM4(af[mt][0], af[mt][1], af[mt][2], af[mt][3],
                      aS + (mt * 16 * TSTRH + kc * 16) * 2);
            LDSM4(bf[0][0], bf[0][1], bf[1][0], bf[1][1], bS + (kc * 16) * 2);
            LDSM4(bf[2][0], bf[2][1], bf[3][0], bf[3][1],
                  bS + (16 * TSTRH + kc * 16) * 2);
#pragma unroll
            for (int mt = 0; mt < 4; mt++)
#pragma unroll
                for (int nt = 0; nt < 4; nt++)
                    mma_f16(acc[mt][nt], af[mt], bf[nt]);
        }
    }
#undef ISSUE

#pragma unroll
    for (int nt = 0; nt < 4; nt++) {
        int col = colBase + wc * 32 + nt * 8 + 2 * lc;
        float2 bb = *(const float2*)&bias[col];
#pragma unroll
        for (int mt = 0; mt < 4; mt++) {
            int row2 = rowBase + wr * 64 + mt * 16 + lr;
#pragma unroll
            for (int half = 0; half < 2; half++) {
                int rr = row2 + half * 8;
                if (rr < NN) {
                    float2 o;
                    o.x = acc[mt][nt][half * 2]     + bb.x;
                    o.y = acc[mt][nt][half * 2 + 1] + bb.y;
                    *(__half2*)&C[(size_t)rr * DD + col] = __float22half2_rn(o);
                }
            }
        }
    }
}

// ---------------- fused 3-GEMM: resident A + flat B stream -------------------
// grid (2, 782): x = colhalf, y = row tile. 24 B-tiles = 3 segs x 8 k-tiles.
__global__ void __launch_bounds__(256, 2) k_mma3r(
    const __half* __restrict__ A,
    const __half* __restrict__ Wh, const float* __restrict__ bh,
    const __half* __restrict__ Wg,
    const __half* __restrict__ Wl, const float* __restrict__ bl,
    const float* __restrict__ attS, const float* __restrict__ attD,
    __half* __restrict__ h, __half* __restrict__ xl)
{
    extern __shared__ __half smh[];
    uint32_t sbA = (uint32_t)__cvta_generic_to_shared(smh);
    uint32_t sbB = sbA + 128 * ASTRH * 2;

    int tid  = threadIdx.x;
    int lane = tid & 31;
    int warp = tid >> 5;
    int wr = warp >> 2, wc = warp & 3;
    int lr = lane >> 2, lc = lane & 3;
    int rowBase = blockIdx.y * GBM;
    int colhalf = blockIdx.x;
    int colBase = colhalf * GBN;

    // --- A load: full 128x256 tile, one cp.async group ---
    int arow = tid >> 1;
    int akp  = (tid & 1) * 128;
    bool okA = (rowBase + arow) < NN;
    {
        const __half* gA = A + (size_t)(rowBase + arow) * DD + akp;
        uint32_t sa = sbA + (arow * ASTRH + akp) * 2;
#pragma unroll
        for (int j = 0; j < 16; j++)
            cpa16(sa + j * 16, gA + j * 8, okA);
    }
    CP_COMMIT();

    // --- B stream: thread t -> row t>>1, 16 halves at (t&1)*16 ---
    int brow = tid >> 1;
    int bkp  = (tid & 1) * 16;

#define ISSUEB(i, s)                                                           \
    do {                                                                       \
        int seg_ = (i) >> 3;                                                   \
        int kt_  = (i) & 7;                                                    \
        const __half* W_ = (seg_ == 0) ? Wh : (seg_ == 1 ? Wg : Wl);           \
        const __half* gB = W_ + (size_t)(colBase + brow) * DD                  \
                             + kt_ * GBK3 + bkp;                               \
        uint32_t sb = sbB + (s) * BT_H * 2 + (brow * TSTRH + bkp) * 2;         \
        cpa16(sb,      gB,     true);                                          \
        cpa16(sb + 16, gB + 8, true);                                          \
        CP_COMMIT();                                                           \
    } while (0)

    ISSUEB(0, 0);
    ISSUEB(1, 1);

    int aOff = (wr * 64 + (lane & 15)) * ASTRH + (lane >> 4) * 8;
    int bOff = (wc * 32 + (lane & 7) + ((lane >> 4) & 1) * 8) * TSTRH
             + ((lane >> 3) & 1) * 8;

    float acc[4][4][4];

    const int NTI = 24;
    for (int i = 0; i < NTI; i++) {
        CP_WAIT1();
        __syncthreads();
        if (i + 2 < NTI) ISSUEB(i + 2, (i + 2) % ST);
        else CP_COMMIT();

        int kt = i & 7;
        if (kt == 0) {
#pragma unroll
            for (int m = 0; m < 4; m++)
#pragma unroll
                for (int n = 0; n < 4; n++)
#pragma unroll
                    for (int r = 0; r < 4; r++) acc[m][n][r] = 0.f;
        }

        int s = i % ST;
        uint32_t bS = sbB + s * BT_H * 2 + bOff * 2;
#pragma unroll
        for (int kc = 0; kc < 2; kc++) {
            int ko = kt * GBK3 + kc * 16;
            uint32_t af[4][4], bf[4][2];
#pragma unroll
            for (int mt = 0; mt < 4; mt++)
                LDSM4(af[mt][0], af[mt][1], af[mt][2], af[mt][3],
                      sbA + (aOff + mt * 16 * ASTRH + ko) * 2);
            LDSM4(bf[0][0], bf[0][1], bf[1][0], bf[1][1], bS + (kc * 16) * 2);
            LDSM4(bf[2][0], bf[2][1], bf[3][0], bf[3][1],
                  bS + (16 * TSTRH + kc * 16) * 2);
#pragma unroll
            for (int mt = 0; mt < 4; mt++)
#pragma unroll
                for (int nt = 0; nt < 4; nt++)
                    mma_f16(acc[mt][nt], af[mt], bf[nt]);
        }

        if (kt == 7) {
            int seg = i >> 3;
            if (seg == 1) {
                // hg fp16 (gatc gather target)
#pragma unroll
                for (int nt = 0; nt < 4; nt++) {
                    int col = colBase + wc * 32 + nt * 8 + 2 * lc;
#pragma unroll
                    for (int mt = 0; mt < 4; mt++) {
                        int row2 = rowBase + wr * 64 + mt * 16 + lr;
#pragma unroll
                        for (int half = 0; half < 2; half++) {
                            int rr = row2 + half * 8;
                            if (rr < NN) {
                                float2 o;
                                o.x = acc[mt][nt][half * 2];
                                o.y = acc[mt][nt][half * 2 + 1];
                                *(__half2*)&g_hgh[(size_t)rr * DD + col] =
                                    __float22half2_rn(o);
                            }
                        }
                    }
                }
                // attention scalar partials
                float2 asw[4], adw[4];
#pragma unroll
                for (int nt = 0; nt < 4; nt++) {
                    int col = colBase + wc * 32 + nt * 8 + 2 * lc;
                    asw[nt] = *(const float2*)&attS[col];
                    adw[nt] = *(const float2*)&attD[col];
                }
                int hh = (colBase + wc * 32) >> 6;
                int slab = wc & 1;
#pragma unroll
                for (int mt = 0; mt < 4; mt++) {
#pragma unroll
                    for (int half = 0; half < 2; half++) {
                        float ps = 0.f, pd = 0.f;
#pragma unroll
                        for (int nt = 0; nt < 4; nt++) {
                            float v0 = acc[mt][nt][half * 2];
                            float v1 = acc[mt][nt][half * 2 + 1];
                            ps = fmaf(v0, asw[nt].x, fmaf(v1, asw[nt].y, ps));
                            pd = fmaf(v0, adw[nt].x, fmaf(v1, adw[nt].y, pd));
                        }
                        ps += __shfl_xor_sync(0xFFFFFFFFu, ps, 1);
                        ps += __shfl_xor_sync(0xFFFFFFFFu, ps, 2);
                        pd += __shfl_xor_sync(0xFFFFFFFFu, pd, 1);
                        pd += __shfl_xor_sync(0xFFFFFFFFu, pd, 2);
                        int rr = rowBase + wr * 64 + mt * 16 + lr + half * 8;
                        if (lc == 0 && rr < NN) {
                            float2 o = make_float2(ps, pd);
                            *(float2*)&g_attp[((size_t)(rr * 4 + hh) * 2 + slab) * 2] = o;
                        }
                    }
                }
            } else {
                bool relu = (seg == 0);
                const float* bias = (seg == 0) ? bh : bl;
                __half* C = (seg == 0) ? h : xl;
#pragma unroll
                for (int nt = 0; nt < 4; nt++) {
                    int col = colBase + wc * 32 + nt * 8 + 2 * lc;
                    float2 bb = *(const float2*)&bias[col];
#pragma unroll
                    for (int mt = 0; mt < 4; mt++) {
                        int row2 = rowBase + wr * 64 + mt * 16 + lr;
#pragma unroll
                        for (int half = 0; half < 2; half++) {
                            int rr = row2 + half * 8;
                            if (rr < NN) {
                                float2 o;
                                o.x = acc[mt][nt][half * 2]     + bb.x;
                                o.y = acc[mt][nt][half * 2 + 1] + bb.y;
                                if (relu) { o.x = fmaxf(o.x, 0.f); o.y = fmaxf(o.y, 0.f); }
                                __stcs((__half2*)&C[(size_t)rr * DD + col],
                                       __float22half2_rn(o));
                            }
                        }
                    }
                }
            }
        }
    }
#undef ISSUEB
}

// ---------------- attention partial reduce ------------------------------------
__global__ void k_attred() {
    int i = blockIdx.x * blockDim.x + threadIdx.x;
    if (i >= NN * HH) return;
    float4 v = *(const float4*)&g_attp[(size_t)i * 4];
    g_asrc[i] = v.x + v.z;
    g_adst[i] = v.y + v.w;
}

// ---------------- GAT + combine fused: warp per node -------------------------
__device__ __forceinline__ float pick4(float4 v, int h) {
    float r = v.x;
    r = (h == 1) ? v.y : r;
    r = (h == 2) ? v.z : r;
    r = (h == 3) ? v.w : r;
    return r;
}

__device__ __forceinline__ void h8(uint4 raw, float* f) {
    float2 a = __half22float2(*(const __half2*)&raw.x);
    float2 b = __half22float2(*(const __half2*)&raw.y);
    float2 c = __half22float2(*(const __half2*)&raw.z);
    float2 d = __half22float2(*(const __half2*)&raw.w);
    f[0]=a.x; f[1]=a.y; f[2]=b.x; f[3]=b.y; f[4]=c.x; f[5]=c.y; f[6]=d.x; f[7]=d.y;
}

__global__ void __launch_bounds__(256) k_gatc(
    const float* __restrict__ bg, const float* __restrict__ lng,
    const float* __restrict__ lnb, const float* __restrict__ betas, int first)
{
    int w = (blockIdx.x * blockDim.x + threadIdx.x) >> 5;
    int lane = threadIdx.x & 31;
    if (w >= NN) return;
    int n = w;
    int h = lane >> 3;
    int colb = lane * 8;

    int beg = g_rowptr[n], end = g_rowptr[n + 1];
    float4 ad4 = *(const float4*)&g_adst[n * 4];
    float adv = pick4(ad4, h);

    float m = -1e30f, s = 0.f;
    float4 acc0 = make_float4(0,0,0,0), acc1 = make_float4(0,0,0,0);

    for (int e = beg; e < end; e++) {
        int src = g_srcs[e];
        float4 as4 = *(const float4*)&g_asrc[src * 4];
        float ev = pick4(as4, h) + adv;
        ev = ev > 0.f ? ev : NEG_SLOPE * ev;
        float nm = fmaxf(m, ev);
        float sc = __expf(m - nm);
        float wg = __expf(ev - nm);
        m = nm;
        s = fmaf(s, sc, wg);
        uint4 raw = *(const uint4*)&g_hgh[(size_t)src * DD + colb];
        float f[8];
        h8(raw, f);
        acc0.x = fmaf(wg, f[0], acc0.x * sc);
        acc0.y = fmaf(wg, f[1], acc0.y * sc);
        acc0.z = fmaf(wg, f[2], acc0.z * sc);
        acc0.w = fmaf(wg, f[3], acc0.w * sc);
        acc1.x = fmaf(wg, f[4], acc1.x * sc);
        acc1.y = fmaf(wg, f[5], acc1.y * sc);
        acc1.z = fmaf(wg, f[6], acc1.z * sc);
        acc1.w = fmaf(wg, f[7], acc1.w * sc);
    }
    float inv = 1.f / s;
    size_t idx = (size_t)n * DD + colb;
    float4 b0 = *(const float4*)&bg[colb];
    float4 b1 = *(const float4*)&bg[colb + 4];
    float xlv[8], hv[8];
    h8(__ldcs((const uint4*)&g_xl[idx]), xlv);
    h8(__ldcs((const uint4*)&g_h[idx]),  hv);

    float xn[8];
    xn[0] = fmaxf(fmaf(acc0.x, inv, b0.x + xlv[0]), 0.f);
    xn[1] = fmaxf(fmaf(acc0.y, inv, b0.y + xlv[1]), 0.f);
    xn[2] = fmaxf(fmaf(acc0.z, inv, b0.z + xlv[2]), 0.f);
    xn[3] = fmaxf(fmaf(acc0.w, inv, b0.w + xlv[3]), 0.f);
    xn[4] = fmaxf(fmaf(acc1.x, inv, b1.x + xlv[4]), 0.f);
    xn[5] = fmaxf(fmaf(acc1.y, inv, b1.y + xlv[5]), 0.f);
    xn[6] = fmaxf(fmaf(acc1.z, inv, b1.z + xlv[6]), 0.f);
    xn[7] = fmaxf(fmaf(acc1.w, inv, b1.w + xlv[7]), 0.f);

    float t[8];
#pragma unroll
    for (int i = 0; i < 8; i++) t[i] = hv[i] * xn[i];

    float sum = 0.f, sq = 0.f;
#pragma unroll
    for (int i = 0; i < 8; i++) { sum += t[i]; sq += t[i] * t[i]; }
#pragma unroll
    for (int o = 16; o; o >>= 1) {
        sum += __shfl_xor_sync(0xFFFFFFFFu, sum, o);
        sq  += __shfl_xor_sync(0xFFFFFFFFu, sq,  o);
    }
    float mean = sum * (1.f / DD);
    float var = sq * (1.f / DD) - mean * mean;
    float rs = rsqrtf(var + LNEPS);

    float4 lg0 = *(const float4*)&lng[colb];
    float4 lg1 = *(const float4*)&lng[colb + 4];
    float4 lb0 = *(const float4*)&lnb[colb];
    float4 lb1 = *(const float4*)&lnb[colb + 4];
    float4 be0 = *(const float4*)&betas[colb];
    float4 be1 = *(const float4*)&betas[colb + 4];
    float lg[8] = {lg0.x, lg0.y, lg0.z, lg0.w, lg1.x, lg1.y, lg1.z, lg1.w};
    float lb[8] = {lb0.x, lb0.y, lb0.z, lb0.w, lb1.x, lb1.y, lb1.z, lb1.w};
    float bev[8] = {be0.x, be0.y, be0.z, be0.w, be1.x, be1.y, be1.z, be1.w};

    float out[8];
#pragma unroll
    for (int i = 0; i < 8; i++) {
        float ln = (t[i] - mean) * rs * lg[i] + lb[i];
        float be = 1.f / (1.f + __expf(-bev[i]));
        out[i] = (1.f - be) * ln + be * xn[i];
    }

    // g_xh fp16 (next-layer GEMM input); xloc full precision
    *(__half2*)&g_xh[idx]     = __float22half2_rn(make_float2(out[0], out[1]));
    *(__half2*)&g_xh[idx + 2] = __float22half2_rn(make_float2(out[2], out[3]));
    *(__half2*)&g_xh[idx + 4] = __float22half2_rn(make_float2(out[4], out[5]));
    *(__half2*)&g_xh[idx + 6] = __float22half2_rn(make_float2(out[6], out[7]));

    float4 o0 = make_float4(out[0], out[1], out[2], out[3]);
    float4 o1 = make_float4(out[4], out[5], out[6], out[7]);
    if (first) {
        __stcs((float4*)&g_xloc[idx],     o0);
        __stcs((float4*)&g_xloc[idx + 4], o1);
    } else {
        float4 l0 = __ldcs((const float4*)&g_xloc[idx]);
        float4 l1 = __ldcs((const float4*)&g_xloc[idx + 4]);
        l0.x += o0.x; l0.y += o0.y; l0.z += o0.z; l0.w += o0.w;
        l1.x += o1.x; l1.y += o1.y; l1.z += o1.z; l1.w += o1.w;
        __stcs((float4*)&g_xloc[idx],     l0);
        __stcs((float4*)&g_xloc[idx + 4], l1);
    }
}

// ---------------- driver -----------------------------------------------------
extern "C" void kernel_launch(void* const* d_in, const int* in_sizes, int n_in,
                              void* d_out, int out_size) {
    const float* x_in   = (const float*)d_in[0];
    const int*   ei     = (const int*)  d_in[1];
    const float* Win    = (const float*)d_in[2];
    const float* b_in   = (const float*)d_in[3];
    const float* Wh     = (const float*)d_in[4];
    const float* bh     = (const float*)d_in[5];
    const float* Wg     = (const float*)d_in[6];
    const float* attS   = (const float*)d_in[7];
    const float* attD   = (const float*)d_in[8];
    const float* bg     = (const float*)d_in[9];
    const float* Wl     = (const float*)d_in[10];
    const float* bl     = (const float*)d_in[11];
    const float* lng    = (const float*)d_in[12];
    const float* lnb    = (const float*)d_in[13];
    const float* betas  = (const float*)d_in[14];
    const float* Wp     = (const float*)d_in[15];
    const float* bp     = (const float*)d_in[16];
    float* out = (float*)d_out;

    cudaFuncSetAttribute(k_mma3r,  cudaFuncAttributeMaxDynamicSharedMemorySize, SMEMR);
    cudaFuncSetAttribute(k_mmaI16, cudaFuncAttributeMaxDynamicSharedMemorySize, SMEM3);

    static cudaStream_t s2 = nullptr;
    static cudaEvent_t evFork = nullptr, evJoin = nullptr;
    if (s2 == nullptr) {
        cudaStreamCreateWithFlags(&s2, cudaStreamNonBlocking);
        cudaEventCreateWithFlags(&evFork, cudaEventDisableTiming);
        cudaEventCreateWithFlags(&evJoin, cudaEventDisableTiming);
    }

    __half* pxin; cudaGetSymbolAddress((void**)&pxin, g_xin);
    __half* pxh;  cudaGetSymbolAddress((void**)&pxh,  g_xh);
    __half* ph;   cudaGetSymbolAddress((void**)&ph,   g_h);
    __half* pxl;  cudaGetSymbolAddress((void**)&pxl,  g_xl);
    float*  pxlo; cudaGetSymbolAddress((void**)&pxlo, g_xloc);
    __half* pwrh; cudaGetSymbolAddress((void**)&pwrh, g_wrh);

    const __half* rWh  = pwrh;
    const __half* rWg  = pwrh + 196608;
    const __half* rWl  = pwrh + 393216;
    const __half* rWin = pwrh + 589824;

    dim3 gI(2, cdiv(NN, GBM));          // (2, 782)
    dim3 gR(2, cdiv(NN, GBM));          // (2, 782): colhalf on x

    // fork: CSR chain on s2
    cudaEventRecord(evFork, 0);
    cudaStreamWaitEvent(s2, evFork, 0);

    k_round<<<cdiv(655360, 256), 256>>>(Wh, Wg, Wl, Win);
    k_xcvt<<<cdiv(NN * DD / 8, 256), 256>>>(x_in);
    k_mmaI16<<<gI, 256, SMEM3>>>(pxin, rWin, b_in, pxh);
    k_init_cnt<<<cdiv(NN, 256), 256, 0, s2>>>();
    k_mma3r<<<gR, 256, SMEMR>>>(pxh, rWh, bh, rWg, rWl, bl, attS, attD, ph, pxl);

    k_hist<<<cdiv(EE, 256), 256, 0, s2>>>(ei);
    int nb = cdiv(NN, 1024);
    k_scan1<<<nb, 1024, 0, s2>>>();
    k_scan2<<<1, 32, 0, s2>>>(nb);
    k_scan3<<<cdiv(NN, 256), 256, 0, s2>>>();
    k_scatter<<<cdiv(EE + NN, 256), 256, 0, s2>>>(ei);
    cudaEventRecord(evJoin, s2);
    cudaStreamWaitEvent(0, evJoin, 0);

    for (int i = 0; i < 3; i++) {
        if (i > 0) {
            k_mma3r<<<gR, 256, SMEMR>>>(pxh, rWh + i * 65536, bh + i * DD,
                                        rWg + i * 65536, rWl + i * 65536, bl + i * DD,
                                        attS + i * DD, attD + i * DD,
                                        ph, pxl);
        }
        k_attred<<<cdiv(NN * HH, 256), 256>>>();
        k_gatc<<<cdiv(NN * 32, 256), 256>>>(bg + i * DD, lng + i * DD,
                                            lnb + i * DD, betas + i * DD, i == 0);
    }

    // out = xloc @ Wp + bp
    k_mmaO<<<cdiv(NN, 128), 256>>>(pxlo, Wp, bp, out);
}